// round 9
// baseline (speedup 1.0000x reference)
#include <cuda_runtime.h>
#include <math.h>
#include <stdint.h>

#define H 2048
#define FOURH 8192
#define NT 256
#define NBLK 512   // all-resident persistent grid (148 SMs x 4 blocks = 592 slots >= 512)

// Device-global scratch + sync state (zero at module load; self-reset per run)
__device__ __align__(16) float g_h[2 * H];      // layer0, layer1 hidden outputs
__device__ __align__(16) float g_pg[2 * FOURH]; // partial gates (+biases) layers 1,2
__device__ int g_ctr[3];                        // work-unit counters per stage
__device__ int g_bar[3];                        // barrier arrive counters (self-resetting)

struct P {
    const float *x, *hid, *cell;
    const float *Wih0, *Whh0, *bih0, *bhh0;
    const float *Wih1, *Whh1, *bih1, *bhh1;
    const float *Wih2, *Whh2, *bih2, *bhh2;
    const float *Wout, *bout;
    float *out;
};

__device__ __forceinline__ float sigmoidf_(float v) { return 1.0f / (1.0f + expf(-v)); }
__device__ __forceinline__ float warp_red(float v) {
    #pragma unroll
    for (int o = 16; o > 0; o >>= 1) v += __shfl_xor_sync(0xffffffffu, v, o);
    return v;
}
__device__ __forceinline__ float d4(float4 a, float4 b) {
    return a.x * b.x + a.y * b.y + a.z * b.z + a.w * b.w;
}
__device__ __forceinline__ uint32_t smem_u32(const void* p) {
    uint32_t a;
    asm("{ .reg .u64 t; cvta.to.shared.u64 t, %1; cvt.u32.u64 %0, t; }" : "=r"(a) : "l"(p));
    return a;
}
__device__ __forceinline__ void cpasync16(uint32_t s, const void* g) {
    asm volatile("cp.async.cg.shared.global [%0], [%1], 16;" :: "r"(s), "l"(g));
}
template<int N> __device__ __forceinline__ void waitg() {
    asm volatile("cp.async.wait_group %0;" :: "n"(N));
}

template<int STAGE>
__device__ __forceinline__ const float* stage_W(const P& p, int u) {
    if (STAGE == 0) {
        int layer = u >> 11;
        return layer == 0 ? p.Whh0 : (layer == 1 ? p.Whh1 : p.Whh2);
    }
    return STAGE == 1 ? p.Wih1 : p.Wih2;
}
template<int STAGE>
__device__ __forceinline__ int stage_j(int u) { return STAGE == 0 ? (u & (H - 1)) : u; }

// Issue one half-unit (2 gate rows = 16 KB) into smem at dst_s; one commit group.
__device__ __forceinline__ void issue_half(const float* W, int j, int ph, uint32_t dst_s) {
    const int t = threadIdx.x;
    const float4* Wf4 = reinterpret_cast<const float4*>(W);
    #pragma unroll
    for (int r = 0; r < 2; r++) {
        const float4* src = Wf4 + (size_t)((2 * ph + r) * H + j) * 512 + t;
        cpasync16(dst_s + (uint32_t)(r * 512 + t) * 16u, src);
        cpasync16(dst_s + (uint32_t)(r * 512 + 256 + t) * 16u, src + 256);
    }
    asm volatile("cp.async.commit_group;");
}

// Each thread reads ONLY its own staged lanes -> no block sync needed for buffers.
__device__ __forceinline__ void compute_half(const float4* bufh, float4 hv0, float4 hv1,
                                             int ph, int par, float (*smp)[8][4]) {
    const int t = threadIdx.x, lane = t & 31, w = t >> 5;
    #pragma unroll
    for (int r = 0; r < 2; r++) {
        float v = d4(bufh[r * 512 + t], hv0) + d4(bufh[r * 512 + 256 + t], hv1);
        v = warp_red(v);
        if (lane == 0) smp[par][w][2 * ph + r] = v;
    }
}

template<int STAGE>
__device__ __forceinline__ void epilogue(const P& p, int u, const float tot[4]) {
    if (STAGE == 0) {
        const int layer = u >> 11, j = u & (H - 1);
        if (layer == 0) {
            const float xv = __ldg(p.x);
            float gate[4];
            #pragma unroll
            for (int g = 0; g < 4; g++) {
                int r = g * H + j;
                gate[g] = tot[g] + xv * __ldg(p.Wih0 + r) + __ldg(p.bih0 + r) + __ldg(p.bhh0 + r);
            }
            float c2 = sigmoidf_(gate[1]) * __ldg(p.cell + j) + sigmoidf_(gate[0]) * tanhf(gate[2]);
            float h2 = sigmoidf_(gate[3]) * tanhf(c2);
            g_h[j] = h2;
            p.out[1 + j] = h2;
            p.out[1 + 3 * H + j] = c2;
        } else {
            const float* bi = layer == 1 ? p.bih1 : p.bih2;
            const float* bb = layer == 1 ? p.bhh1 : p.bhh2;
            float* pg = g_pg + (layer - 1) * FOURH;
            #pragma unroll
            for (int g = 0; g < 4; g++) {
                int r = g * H + j;
                pg[r] = tot[g] + __ldg(bi + r) + __ldg(bb + r);
            }
        }
    } else {
        const int j = u, layer = STAGE;
        const float* pg = g_pg + (layer - 1) * FOURH;
        float gate[4];
        #pragma unroll
        for (int g = 0; g < 4; g++) gate[g] = tot[g] + __ldcg(pg + g * H + j);
        float c2 = sigmoidf_(gate[1]) * __ldg(p.cell + layer * H + j)
                 + sigmoidf_(gate[0]) * tanhf(gate[2]);
        float h2 = sigmoidf_(gate[3]) * tanhf(c2);
        p.out[1 + layer * H + j] = h2;
        p.out[1 + 3 * H + layer * H + j] = c2;
        if (STAGE == 1) g_h[H + j] = h2;
        else atomicAdd(&p.out[0], h2 * __ldg(p.Wout + j));
    }
}

// All-resident barrier; self-resets (release condition: count hits NBLK OR got reset to 0).
__device__ __forceinline__ void gbar(int i) {
    __syncthreads();
    if (threadIdx.x == 0) {
        __threadfence();
        int v = atomicAdd(&g_bar[i], 1);
        if (v == NBLK - 1) {
            if (i == 2) { g_ctr[0] = 0; g_ctr[1] = 0; g_ctr[2] = 0; __threadfence(); }
            atomicExch(&g_bar[i], 0);
        } else {
            for (;;) {
                int b = *(volatile int*)&g_bar[i];
                if (b == 0 || b >= NBLK) break;
                __nanosleep(32);
            }
        }
    }
    __syncthreads();
}

template<int STAGE>
__device__ __forceinline__ void run_stage(const P& p, uint32_t buf_s, float4* buf,
                                          float (*smp)[8][4], int* su) {
    const int t = threadIdx.x;
    const int limit = (STAGE == 0) ? 3 * H : H;
    int* ctr = &g_ctr[STAGE];

    if (t == 0) su[0] = atomicAdd(ctr, 1);
    __syncthreads();
    int ucur = su[0];
    if (ucur < limit) {
        const float* W = stage_W<STAGE>(p, ucur);
        const int j = stage_j<STAGE>(ucur);
        issue_half(W, j, 0, buf_s);
        issue_half(W, j, 1, buf_s + 16384u);
    }
    if (t == 0) su[1] = atomicAdd(ctr, 1);
    __syncthreads();
    int unext = su[1];
    int kpar = 0;

    while (ucur < limit) {
        const float* hp = (STAGE == 0) ? (p.hid + (ucur >> 11) * H) : (g_h + (STAGE - 1) * H);
        const float4* h4 = reinterpret_cast<const float4*>(hp);
        float4 hv0, hv1;
        if (STAGE == 0) { hv0 = __ldg(h4 + t);  hv1 = __ldg(h4 + t + NT); }
        else            { hv0 = __ldcg(h4 + t); hv1 = __ldcg(h4 + t + NT); }

        const float* Wn = nullptr; int jn = 0;
        if (unext < limit) { Wn = stage_W<STAGE>(p, unext); jn = stage_j<STAGE>(unext); }

        waitg<1>();                                    // half0(cur) ready
        compute_half(buf, hv0, hv1, 0, kpar, smp);
        if (unext < limit) { issue_half(Wn, jn, 0, buf_s); waitg<1>(); }  // half1(cur) ready
        else               { waitg<0>(); }
        compute_half(buf + 1024, hv0, hv1, 1, kpar, smp);
        if (unext < limit) issue_half(Wn, jn, 1, buf_s + 16384u);

        if (t == 0) su[kpar] = atomicAdd(ctr, 1);
        __syncthreads();
        if (t == 0) {
            float tot[4];
            #pragma unroll
            for (int g = 0; g < 4; g++)
                tot[g] = smp[kpar][0][g] + smp[kpar][1][g] + smp[kpar][2][g] + smp[kpar][3][g]
                       + smp[kpar][4][g] + smp[kpar][5][g] + smp[kpar][6][g] + smp[kpar][7][g];
            epilogue<STAGE>(p, ucur, tot);
        }
        int unn = su[kpar];
        ucur = unext; unext = unn; kpar ^= 1;
    }
    gbar(STAGE);
}

__global__ void __launch_bounds__(NT, 4) k_persist(P p) {
    __shared__ float4 buf[2][1024];   // 2 x 16 KB double buffer
    __shared__ float smp[2][8][4];    // parity-buffered warp partials
    __shared__ int su[2];             // parity-buffered unit-index broadcast

    if (blockIdx.x == 0 && threadIdx.x == 0) p.out[0] = __ldg(p.bout);

    uint32_t buf_s = smem_u32(buf);
    run_stage<0>(p, buf_s, &buf[0][0], smp, su);
    run_stage<1>(p, buf_s, &buf[0][0], smp, su);
    run_stage<2>(p, buf_s, &buf[0][0], smp, su);
}

extern "C" void kernel_launch(void* const* d_in, const int* in_sizes, int n_in,
                              void* d_out, int out_size) {
    P p;
    p.x    = (const float*)d_in[0];
    p.hid  = (const float*)d_in[1];
    p.cell = (const float*)d_in[2];
    p.Wih0 = (const float*)d_in[3];
    p.Whh0 = (const float*)d_in[4];
    p.bih0 = (const float*)d_in[5];
    p.bhh0 = (const float*)d_in[6];
    p.Wih1 = (const float*)d_in[7];
    p.Whh1 = (const float*)d_in[8];
    p.bih1 = (const float*)d_in[9];
    p.bhh1 = (const float*)d_in[10];
    p.Wih2 = (const float*)d_in[11];
    p.Whh2 = (const float*)d_in[12];
    p.bih2 = (const float*)d_in[13];
    p.bhh2 = (const float*)d_in[14];
    p.Wout = (const float*)d_in[15];
    p.bout = (const float*)d_in[16];
    p.out  = (float*)d_out;

    k_persist<<<NBLK, NT>>>(p);
}